// round 14
// baseline (speedup 1.0000x reference)
#include <cuda_runtime.h>
#include <cuda_fp16.h>
#include <cstdint>

#define BB 8
#define CIN 128
#define COUT 128
#define HH 64
#define WW 64
#define KK 16
#define HO 61
#define WO 61
#define NPIX (HO * WO)        // 3721
#define MT 128
#define MTILES 30
#define NCHUNK 64             // K chunks of 32

#define AS_BUF 2048           // words per A buffer: 128 rows x 16 words (8192 B)

// ---- smem layout (bytes)
#define SM_AS    0                        // 2 x 8192 = 16384
#define SM_BS    16384                    // 2 x 8192 = 16384
#define SM_BIAS  (16384 + 16384)          // 512
#define SMEM_TOTAL (16384 + 16384 + 512)  // 33280

// Scratch (allocation-free: __device__ globals)
__device__ __half g_inT[(size_t)BB * HH * WW * CIN];    // NHWC input, fp16, 8.4 MB
__device__ uint32_t g_wb[(size_t)NCHUNK * 2048];        // frag-packed fp16 weights, 512 KB

static __device__ __forceinline__ void mma16(float* d, const uint32_t* a, const uint32_t* b) {
    asm volatile(
        "mma.sync.aligned.m16n8k16.row.col.f32.f16.f16.f32 "
        "{%0,%1,%2,%3}, {%4,%5,%6,%7}, {%8,%9}, {%0,%1,%2,%3};"
        : "+f"(d[0]), "+f"(d[1]), "+f"(d[2]), "+f"(d[3])
        : "r"(a[0]), "r"(a[1]), "r"(a[2]), "r"(a[3]), "r"(b[0]), "r"(b[1]));
}
static __device__ __forceinline__ void ldsm4(uint32_t* r, uint32_t addr) {
    asm volatile("ldmatrix.sync.aligned.m8n8.x4.shared.b16 {%0,%1,%2,%3}, [%4];"
                 : "=r"(r[0]), "=r"(r[1]), "=r"(r[2]), "=r"(r[3]) : "r"(addr));
}
static __device__ __forceinline__ void cp16(uint32_t dst, const void* src) {
    asm volatile("cp.async.cg.shared.global [%0], [%1], 16;" :: "r"(dst), "l"(src));
}
static __device__ __forceinline__ void cp_commit() {
    asm volatile("cp.async.commit_group;" ::: "memory");
}
static __device__ __forceinline__ void cp_wait0() {
    asm volatile("cp.async.wait_group 0;" ::: "memory");
}

// ---------------------------------------------------------------------------
// Kernel 1: NCHW fp32 -> NHWC fp16 transpose
// ---------------------------------------------------------------------------
__global__ void transpose_kernel(const float* __restrict__ inp) {
    __shared__ float tile[CIN][WW + 1];
    int by = blockIdx.x;
    int b = by / HH, y = by % HH;
    const float* src = inp + (size_t)b * CIN * HH * WW + (size_t)y * WW;
    for (int i = threadIdx.x; i < CIN * WW; i += blockDim.x) {
        int c = i / WW, x = i % WW;
        tile[c][x] = src[(size_t)c * HH * WW + x];
    }
    __syncthreads();
    __half* dst = g_inT + ((size_t)b * HH + y) * WW * CIN;
    for (int i = threadIdx.x; i < CIN * WW; i += blockDim.x) {
        int x = i / CIN, c = i % CIN;
        dst[(size_t)x * CIN + c] = __float2half(tile[c][x]);
    }
}

// ---------------------------------------------------------------------------
// Kernel 2: weight flip + fp16 + pack in m16n8k16 B-fragment order.
// ---------------------------------------------------------------------------
__global__ void wpack_kernel(const float* __restrict__ wgt) {
    int idx = blockIdx.x * blockDim.x + threadIdx.x;
    if (idx >= NCHUNK * 2048) return;
    int r    = idx & 1;
    int lane = (idx >> 1) & 31;
    int na   = (idx >> 6) & 15;
    int s    = (idx >> 10) & 1;
    int t    = idx >> 11;
    int n = na * 8 + (lane >> 2);
    int k0 = s * 16 + (lane & 3) * 2 + r * 8;
    int dk = t >> 2;
    int ki = dk >> 2, kj = dk & 3;
    size_t base = ((size_t)n * CIN + (t & 3) * 32 + k0) * 16 + (3 - ki) * 4 + (3 - kj);
    float v0 = wgt[base];
    float v1 = wgt[base + 16];
    __half2 h2 = __floats2half2_rn(v0, v1);
    g_wb[idx] = *(uint32_t*)&h2;
}

// ---------------------------------------------------------------------------
// Kernel 3: fused bilinear sample (fp16) + fp16 m16n8k16 mma GEMM.
// A tile: [px][16 words], 64B rows, XOR swizzle gp = g ^ ((px>>1)&3).
//   word group g (16B) holds channels g*8..g*8+7 of the 32-ch chunk.
// ---------------------------------------------------------------------------
__global__ void __launch_bounds__(256, 2)
main_kernel(const float* __restrict__ offset, const float* __restrict__ mask,
            const float* __restrict__ bias, float* __restrict__ out) {
    extern __shared__ char smem[];
    uint32_t* As = (uint32_t*)(smem + SM_AS);   // [2][128][16] words, swizzled
    uint32_t* Bs = (uint32_t*)(smem + SM_BS);   // [2][2048]
    float* bias_s = (float*)(smem + SM_BIAS);
    const uint32_t as_u32 = (uint32_t)__cvta_generic_to_shared(As);

    const int tid = threadIdx.x;
    const int mtile = blockIdx.x;
    const int b = blockIdx.y;
    const int lane = tid & 31;
    const int wid = tid >> 5;
    const int mw = wid & 3, nw = wid >> 2;

    if (tid < COUT) bias_s[tid] = bias[tid];

    // fill-thread mapping: 2 threads per pixel, 16 channels each
    const int px = tid >> 1;
    const int h = tid & 1;
    const int p = mtile * MT + px;
    const bool pvalid = p < NPIX;
    const int oh = pvalid ? p / WO : 0;
    const int ow = pvalid ? p % WO : 0;
    const __half* inTb = g_inT + (size_t)b * HH * WW * CIN;

    // ldmatrix lane-address pieces (constant per thread)
    const int lt = lane >> 3, lr = lane & 7;

    float acc[2][8][4];
#pragma unroll
    for (int i = 0; i < 2; ++i)
#pragma unroll
        for (int j = 0; j < 8; ++j)
#pragma unroll
            for (int e = 0; e < 4; ++e) acc[i][j][e] = 0.f;

    float4 wv = {0.f, 0.f, 0.f, 0.f};
    int4 bv = {0, 0, 0, 0};
    float pdy = 0.f, pdx = 0.f, pmk = 0.f;

    auto calc_params = [&](int dk, float dy, float dx, float mk) {
        wv = make_float4(0.f, 0.f, 0.f, 0.f);
        bv = make_int4(0, 0, 0, 0);
        if (pvalid) {
            int ki = dk >> 2, kj = dk & 3;
            float y = dy + (float)(ki + oh);
            float x = dx + (float)(kj + ow);
            float y0f = floorf(y), x0f = floorf(x);
            int y0 = (int)y0f, x0 = (int)x0f;
            float wy = y - y0f, wx = x - x0f;
            float w00 = (1.f - wy) * (1.f - wx) * mk;
            float w01 = (1.f - wy) * wx * mk;
            float w10 = wy * (1.f - wx) * mk;
            float w11 = wy * wx * mk;
            bool vy0 = (y0 >= 0) && (y0 < HH);
            bool vy1 = (y0 + 1 >= 0) && (y0 + 1 < HH);
            bool vx0 = (x0 >= 0) && (x0 < WW);
            bool vx1 = (x0 + 1 >= 0) && (x0 + 1 < WW);
            wv.x = (vy0 && vx0) ? w00 : 0.f;
            wv.y = (vy0 && vx1) ? w01 : 0.f;
            wv.z = (vy1 && vx0) ? w10 : 0.f;
            wv.w = (vy1 && vx1) ? w11 : 0.f;
            int y0c = min(max(y0, 0), HH - 1), y1c = min(max(y0 + 1, 0), HH - 1);
            int x0c = min(max(x0, 0), WW - 1), x1c = min(max(x0 + 1, 0), WW - 1);
            bv.x = (y0c * WW + x0c) * CIN;
            bv.y = (y0c * WW + x1c) * CIN;
            bv.z = (y1c * WW + x0c) * CIN;
            bv.w = (y1c * WW + x1c) * CIN;
        }
    };
    auto prefetch_om = [&](int dk) {
        if (pvalid && dk < KK) {
            size_t ob = (((size_t)b * 2 * KK + 2 * dk) * HO + oh) * WO + ow;
            pdy = offset[ob];
            pdx = offset[ob + (size_t)HO * WO];
            pmk = mask[(((size_t)b * KK + dk) * HO + oh) * WO + ow];
        }
    };
    // interp 8 channels (fp32 math), one swizzled STS.128
    auto interp_store = [&](uint32_t* An, int s, const uint4& ga, const uint4& gb,
                            const uint4& gc, const uint4& gd) {
        const __half2* ha = (const __half2*)&ga;
        const __half2* hb = (const __half2*)&gb;
        const __half2* hc = (const __half2*)&gc;
        const __half2* hd = (const __half2*)&gd;
        uint4 r4;
        uint32_t* rw = (uint32_t*)&r4;
#pragma unroll
        for (int w = 0; w < 4; ++w) {
            float2 a = __half22float2(ha[w]);
            float2 b2 = __half22float2(hb[w]);
            float2 c2 = __half22float2(hc[w]);
            float2 d2 = __half22float2(hd[w]);
            float lo = wv.x * a.x + wv.y * b2.x + wv.z * c2.x + wv.w * d2.x;
            float hi = wv.x * a.y + wv.y * b2.y + wv.z * c2.y + wv.w * d2.y;
            __half2 o = __floats2half2_rn(lo, hi);
            rw[w] = *(uint32_t*)&o;
        }
        const int gp = (h * 2 + s) ^ ((px >> 1) & 3);
        *(uint4*)&An[px * 16 + gp * 4] = r4;
    };

    // ---- prologue: params dk0, prefetch dk1, fill chunk 0 into buffer 0 ----
    {
        float dy0 = 0.f, dx0 = 0.f, mk0 = 0.f;
        if (pvalid) {
            size_t ob = (((size_t)b * 2 * KK) * HO + oh) * WO + ow;
            dy0 = offset[ob];
            dx0 = offset[ob + (size_t)HO * WO];
            mk0 = mask[(((size_t)b * KK) * HO + oh) * WO + ow];
        }
        calc_params(0, dy0, dx0, mk0);
        prefetch_om(1);
        {
            const float4* src = (const float4*)g_wb;
            uint32_t d0 = (uint32_t)__cvta_generic_to_shared(Bs);
#pragma unroll
            for (int j = 0; j < 2; ++j)
                cp16(d0 + (uint32_t)(tid + j * 256) * 16, src + tid + j * 256);
            cp_commit();
        }
#pragma unroll
        for (int s = 0; s < 2; ++s) {
            const int c0 = h * 16 + s * 8;
            uint4 ga = *(const uint4*)(inTb + bv.x + c0);
            uint4 gb = *(const uint4*)(inTb + bv.y + c0);
            uint4 gc = *(const uint4*)(inTb + bv.z + c0);
            uint4 gd = *(const uint4*)(inTb + bv.w + c0);
            interp_store(As, s, ga, gb, gc, gd);
        }
        cp_wait0();
        __syncthreads();
    }

    // ---- main loop ----
    for (int t = 0; t < NCHUNK; ++t) {
        const int cur = t & 1;
        const uint32_t abase = as_u32 + cur * (AS_BUF * 4);
        const uint32_t* Bcu = Bs + cur * 2048;
        uint32_t* An = As + (cur ^ 1) * AS_BUF;
        const bool hn = (t < NCHUNK - 1);

        int c0n = 0;
        uint4 ga, gb, gc, gd;
        if (hn) {
            if (((t + 1) & 3) == 0) {
                int dkn = (t + 1) >> 2;
                calc_params(dkn, pdy, pdx, pmk);
                prefetch_om(dkn + 1);
            }
            const float4* src = (const float4*)(g_wb + (size_t)(t + 1) * 2048);
            uint32_t d0 = (uint32_t)__cvta_generic_to_shared(Bs + (cur ^ 1) * 2048);
#pragma unroll
            for (int j = 0; j < 2; ++j)
                cp16(d0 + (uint32_t)(tid + j * 256) * 16, src + tid + j * 256);
            cp_commit();
            c0n = ((t + 1) & 3) * 32 + h * 16;
            ga = *(const uint4*)(inTb + bv.x + c0n);
            gb = *(const uint4*)(inTb + bv.y + c0n);
            gc = *(const uint4*)(inTb + bv.z + c0n);
            gd = *(const uint4*)(inTb + bv.w + c0n);
        }

#pragma unroll
        for (int s = 0; s < 2; ++s) {
            // A fragments via ldmatrix.x4 (swizzled, conflict-free)
            uint32_t af[2][4];
#pragma unroll
            for (int ma = 0; ma < 2; ++ma) {
                const int m = (mw * 2 + ma) * 16 + (lt & 1) * 8 + lr;
                const int g = 2 * s + (lt >> 1);
                const int gp = g ^ ((m >> 1) & 3);
                ldsm4(af[ma], abase + (uint32_t)(m * 64 + gp * 16));
            }
            // B fragments (LDS.64, frag-ordered)
            uint32_t bf[8][2];
#pragma unroll
            for (int na = 0; na < 8; ++na) {
                uint2 v = *(const uint2*)&Bcu[((s * 16 + nw * 8 + na) * 32 + lane) * 2];
                bf[na][0] = v.x; bf[na][1] = v.y;
            }
            // MMA
#pragma unroll
            for (int ma = 0; ma < 2; ++ma)
#pragma unroll
                for (int na = 0; na < 8; ++na)
                    mma16(acc[ma][na], af[ma], bf[na]);

            // consume gather group s -> store into next A buffer, issue group s+1
            if (hn) {
                interp_store(An, s, ga, gb, gc, gd);
                if (s == 0) {
                    ga = *(const uint4*)(inTb + bv.x + c0n + 8);
                    gb = *(const uint4*)(inTb + bv.y + c0n + 8);
                    gc = *(const uint4*)(inTb + bv.z + c0n + 8);
                    gd = *(const uint4*)(inTb + bv.w + c0n + 8);
                }
            }
        }
        cp_wait0();
        __syncthreads();
    }

    // ---- epilogue: stage through smem for coalesced NCHW writes ----
    float* Cs = (float*)smem;   // 64 n x 128 m = 32 KB
    float* ob = out + (size_t)b * COUT * NPIX;
#pragma unroll 1
    for (int nhalf = 0; nhalf < 2; ++nhalf) {
        if (nw == nhalf) {
#pragma unroll
            for (int ma = 0; ma < 2; ++ma)
#pragma unroll
                for (int na = 0; na < 8; ++na)
#pragma unroll
                    for (int d = 0; d < 4; ++d) {
                        int nl = na * 8 + (lane & 3) * 2 + (d & 1);
                        int m = (mw * 2 + ma) * 16 + (lane >> 2) + 8 * (d >> 1);
                        Cs[nl * 128 + m] = acc[ma][na][d];
                    }
        }
        __syncthreads();
#pragma unroll
        for (int it = 0; it < 32; ++it) {
            int idx = tid + it * 256;
            int nl = idx >> 7, m = idx & 127;
            int pp = mtile * MT + m;
            int n = nhalf * 64 + nl;
            if (pp < NPIX)
                ob[(size_t)n * NPIX + pp] = Cs[idx] + bias_s[n];
        }
        __syncthreads();
    }
}

// ---------------------------------------------------------------------------
extern "C" void kernel_launch(void* const* d_in, const int* in_sizes, int n_in,
                              void* d_out, int out_size) {
    const float* inp    = (const float*)d_in[0];
    const float* offset = (const float*)d_in[1];
    const float* mask   = (const float*)d_in[2];
    const float* weight = (const float*)d_in[3];
    const float* bias   = (const float*)d_in[4];
    float* out = (float*)d_out;

    cudaFuncSetAttribute(main_kernel, cudaFuncAttributeMaxDynamicSharedMemorySize,
                         SMEM_TOTAL);

    transpose_kernel<<<BB * HH, 256>>>(inp);
    wpack_kernel<<<(NCHUNK * 2048 + 255) / 256, 256>>>(weight);
    main_kernel<<<dim3(MTILES, BB), 256, SMEM_TOTAL>>>(offset, mask, bias, out);
}

// round 16
// speedup vs baseline: 1.4478x; 1.4478x over previous
#include <cuda_runtime.h>
#include <cuda_fp16.h>
#include <cstdint>

#define BB 8
#define CIN 128
#define COUT 128
#define HH 64
#define WW 64
#define KK 16
#define HO 61
#define WO 61
#define NPIX (HO * WO)        // 3721
#define MT 128
#define MTILES 30
#define NCHUNK 64             // K chunks of 32

#define SLD 136               // As row stride in words (half2 units per k2-row)
#define AS_BUF (16 * SLD)     // words per A buffer (16 k2-rows) = 8704 B

// ---- smem layout (bytes)
#define SM_AS    0                        // 2 x 8704 = 17408
#define SM_BS    17408                    // 2 x 8192 = 16384
#define SM_BIAS  (17408 + 16384)          // 512
#define SMEM_TOTAL (17408 + 16384 + 512)  // 34304

// Scratch (allocation-free: __device__ globals)
__device__ __half g_inT[(size_t)BB * HH * WW * CIN];    // NHWC input, fp16, 8.4 MB
__device__ uint32_t g_wb[(size_t)NCHUNK * 2048];        // frag-packed fp16 weights, 512 KB

static __device__ __forceinline__ void mma16(float* d, const uint32_t* a, const uint32_t* b) {
    asm volatile(
        "mma.sync.aligned.m16n8k16.row.col.f32.f16.f16.f32 "
        "{%0,%1,%2,%3}, {%4,%5,%6,%7}, {%8,%9}, {%0,%1,%2,%3};"
        : "+f"(d[0]), "+f"(d[1]), "+f"(d[2]), "+f"(d[3])
        : "r"(a[0]), "r"(a[1]), "r"(a[2]), "r"(a[3]), "r"(b[0]), "r"(b[1]));
}
static __device__ __forceinline__ void cp16(uint32_t dst, const void* src) {
    asm volatile("cp.async.cg.shared.global [%0], [%1], 16;" :: "r"(dst), "l"(src));
}
static __device__ __forceinline__ void cp_commit() {
    asm volatile("cp.async.commit_group;" ::: "memory");
}
static __device__ __forceinline__ void cp_wait0() {
    asm volatile("cp.async.wait_group 0;" ::: "memory");
}

// ---------------------------------------------------------------------------
// Kernel 1: NCHW fp32 -> NHWC fp16 transpose
// ---------------------------------------------------------------------------
__global__ void transpose_kernel(const float* __restrict__ inp) {
    __shared__ float tile[CIN][WW + 1];
    int by = blockIdx.x;
    int b = by / HH, y = by % HH;
    const float* src = inp + (size_t)b * CIN * HH * WW + (size_t)y * WW;
    for (int i = threadIdx.x; i < CIN * WW; i += blockDim.x) {
        int c = i / WW, x = i % WW;
        tile[c][x] = src[(size_t)c * HH * WW + x];
    }
    __syncthreads();
    __half* dst = g_inT + ((size_t)b * HH + y) * WW * CIN;
    for (int i = threadIdx.x; i < CIN * WW; i += blockDim.x) {
        int x = i / CIN, c = i % CIN;
        dst[(size_t)x * CIN + c] = __float2half(tile[c][x]);
    }
}

// ---------------------------------------------------------------------------
// Kernel 2: weight flip + fp16 + pack in m16n8k16 B-fragment order,
// LDS.128-friendly: word idx = ((s*8 + na2)*32 + lane)*4 + w, where
//   na_global = na2*2 + (w>>1), r = w&1
//   n = na_global*8 + lane>>2 ; k_local = s*16 + (lane&3)*2 + r*8 + {0,1}
//   c = (t&3)*32 + k_local ; dk = t>>2 (spatially flipped)
// ---------------------------------------------------------------------------
__global__ void wpack_kernel(const float* __restrict__ wgt) {
    int idx = blockIdx.x * blockDim.x + threadIdx.x;
    if (idx >= NCHUNK * 2048) return;
    int w    = idx & 3;
    int lane = (idx >> 2) & 31;
    int na2  = (idx >> 7) & 7;
    int s    = (idx >> 10) & 1;
    int t    = idx >> 11;
    int na_g = na2 * 2 + (w >> 1);
    int r    = w & 1;
    int n = na_g * 8 + (lane >> 2);
    int k0 = s * 16 + (lane & 3) * 2 + r * 8;
    int dk = t >> 2;
    int ki = dk >> 2, kj = dk & 3;
    size_t base = ((size_t)n * CIN + (t & 3) * 32 + k0) * 16 + (3 - ki) * 4 + (3 - kj);
    float v0 = wgt[base];
    float v1 = wgt[base + 16];
    __half2 h2 = __floats2half2_rn(v0, v1);
    g_wb[idx] = *(uint32_t*)&h2;
}

// ---------------------------------------------------------------------------
// Kernel 3: fused bilinear sample (fp16) + fp16 m16n8k16 mma GEMM.
// ---------------------------------------------------------------------------
__global__ void __launch_bounds__(256, 2)
main_kernel(const float* __restrict__ offset, const float* __restrict__ mask,
            const float* __restrict__ bias, float* __restrict__ out) {
    extern __shared__ char smem[];
    uint32_t* As = (uint32_t*)(smem + SM_AS);   // [2][16 k2][SLD] half2 words
    uint32_t* Bs = (uint32_t*)(smem + SM_BS);   // [2][2048]
    float* bias_s = (float*)(smem + SM_BIAS);

    const int tid = threadIdx.x;
    const int mtile = blockIdx.x;
    const int b = blockIdx.y;
    const int lane = tid & 31;
    const int wid = tid >> 5;
    const int mw = wid & 3, nw = wid >> 2;

    if (tid < COUT) bias_s[tid] = bias[tid];

    // fill-thread mapping: 2 threads per pixel, 16 channels each
    const int px = tid >> 1;
    const int h = tid & 1;
    const int p = mtile * MT + px;
    const bool pvalid = p < NPIX;
    const int oh = pvalid ? p / WO : 0;
    const int ow = pvalid ? p % WO : 0;
    const __half* inTb = g_inT + (size_t)b * HH * WW * CIN;

    float acc[2][8][4];
#pragma unroll
    for (int i = 0; i < 2; ++i)
#pragma unroll
        for (int j = 0; j < 8; ++j)
#pragma unroll
            for (int e = 0; e < 4; ++e) acc[i][j][e] = 0.f;

    float4 wv = {0.f, 0.f, 0.f, 0.f};
    int4 bv = {0, 0, 0, 0};
    float pdy = 0.f, pdx = 0.f, pmk = 0.f;

    auto calc_params = [&](int dk, float dy, float dx, float mk) {
        wv = make_float4(0.f, 0.f, 0.f, 0.f);
        bv = make_int4(0, 0, 0, 0);
        if (pvalid) {
            int ki = dk >> 2, kj = dk & 3;
            float y = dy + (float)(ki + oh);
            float x = dx + (float)(kj + ow);
            float y0f = floorf(y), x0f = floorf(x);
            int y0 = (int)y0f, x0 = (int)x0f;
            float wy = y - y0f, wx = x - x0f;
            float w00 = (1.f - wy) * (1.f - wx) * mk;
            float w01 = (1.f - wy) * wx * mk;
            float w10 = wy * (1.f - wx) * mk;
            float w11 = wy * wx * mk;
            bool vy0 = (y0 >= 0) && (y0 < HH);
            bool vy1 = (y0 + 1 >= 0) && (y0 + 1 < HH);
            bool vx0 = (x0 >= 0) && (x0 < WW);
            bool vx1 = (x0 + 1 >= 0) && (x0 + 1 < WW);
            wv.x = (vy0 && vx0) ? w00 : 0.f;
            wv.y = (vy0 && vx1) ? w01 : 0.f;
            wv.z = (vy1 && vx0) ? w10 : 0.f;
            wv.w = (vy1 && vx1) ? w11 : 0.f;
            int y0c = min(max(y0, 0), HH - 1), y1c = min(max(y0 + 1, 0), HH - 1);
            int x0c = min(max(x0, 0), WW - 1), x1c = min(max(x0 + 1, 0), WW - 1);
            bv.x = (y0c * WW + x0c) * CIN;
            bv.y = (y0c * WW + x1c) * CIN;
            bv.z = (y1c * WW + x0c) * CIN;
            bv.w = (y1c * WW + x1c) * CIN;
        }
    };
    auto prefetch_om = [&](int dk) {
        if (pvalid && dk < KK) {
            size_t ob = (((size_t)b * 2 * KK + 2 * dk) * HO + oh) * WO + ow;
            pdy = offset[ob];
            pdx = offset[ob + (size_t)HO * WO];
            pmk = mask[(((size_t)b * KK + dk) * HO + oh) * WO + ow];
        }
    };
    // interp 8 channels (fp32 math), store 4 half2 words
    auto interp_store = [&](uint32_t* An, int s, const uint4& ga, const uint4& gb,
                            const uint4& gc, const uint4& gd) {
        const __half2* ha = (const __half2*)&ga;
        const __half2* hb = (const __half2*)&gb;
        const __half2* hc = (const __half2*)&gc;
        const __half2* hd = (const __half2*)&gd;
#pragma unroll
        for (int w = 0; w < 4; ++w) {
            float2 a = __half22float2(ha[w]);
            float2 b2 = __half22float2(hb[w]);
            float2 c2 = __half22float2(hc[w]);
            float2 d2 = __half22float2(hd[w]);
            float lo = wv.x * a.x + wv.y * b2.x + wv.z * c2.x + wv.w * d2.x;
            float hi = wv.x * a.y + wv.y * b2.y + wv.z * c2.y + wv.w * d2.y;
            __half2 o = __floats2half2_rn(lo, hi);
            An[(h * 8 + s * 4 + w) * SLD + px] = *(uint32_t*)&o;
        }
    };

    // ---- prologue: params dk0, prefetch dk1, fill chunk 0 into buffer 0 ----
    {
        float dy0 = 0.f, dx0 = 0.f, mk0 = 0.f;
        if (pvalid) {
            size_t ob = (((size_t)b * 2 * KK) * HO + oh) * WO + ow;
            dy0 = offset[ob];
            dx0 = offset[ob + (size_t)HO * WO];
            mk0 = mask[(((size_t)b * KK) * HO + oh) * WO + ow];
        }
        calc_params(0, dy0, dx0, mk0);
        prefetch_om(1);
        {
            const float4* src = (const float4*)g_wb;
            uint32_t d0 = (uint32_t)__cvta_generic_to_shared(Bs);
#pragma unroll
            for (int j = 0; j < 2; ++j)
                cp16(d0 + (uint32_t)(tid + j * 256) * 16, src + tid + j * 256);
            cp_commit();
        }
#pragma unroll
        for (int s = 0; s < 2; ++s) {
            const int c0 = h * 16 + s * 8;
            uint4 ga = *(const uint4*)(inTb + bv.x + c0);
            uint4 gb = *(const uint4*)(inTb + bv.y + c0);
            uint4 gc = *(const uint4*)(inTb + bv.z + c0);
            uint4 gd = *(const uint4*)(inTb + bv.w + c0);
            interp_store(As, s, ga, gb, gc, gd);
        }
        cp_wait0();
        __syncthreads();
    }

    // ---- main loop ----
    for (int t = 0; t < NCHUNK; ++t) {
        const int cur = t & 1;
        const uint32_t* Acu = As + cur * AS_BUF;
        const uint32_t* Bcu = Bs + cur * 2048;
        uint32_t* An = As + (cur ^ 1) * AS_BUF;
        const bool hn = (t < NCHUNK - 1);

        int c0n = 0;
        uint4 ga, gb, gc, gd;
        if (hn) {
            if (((t + 1) & 3) == 0) {
                int dkn = (t + 1) >> 2;
                calc_params(dkn, pdy, pdx, pmk);
                prefetch_om(dkn + 1);
            }
            const float4* src = (const float4*)(g_wb + (size_t)(t + 1) * 2048);
            uint32_t d0 = (uint32_t)__cvta_generic_to_shared(Bs + (cur ^ 1) * 2048);
#pragma unroll
            for (int j = 0; j < 2; ++j)
                cp16(d0 + (uint32_t)(tid + j * 256) * 16, src + tid + j * 256);
            cp_commit();
            c0n = ((t + 1) & 3) * 32 + h * 16;
            ga = *(const uint4*)(inTb + bv.x + c0n);
            gb = *(const uint4*)(inTb + bv.y + c0n);
            gc = *(const uint4*)(inTb + bv.z + c0n);
            gd = *(const uint4*)(inTb + bv.w + c0n);
        }

#pragma unroll
        for (int s = 0; s < 2; ++s) {
            // A fragments (conflict-free LDS.32)
            uint32_t af[2][4];
            {
                const int k2 = s * 8 + (lane & 3);
                const int mbase = mw * 32 + (lane >> 2);
#pragma unroll
                for (int ma = 0; ma < 2; ++ma) {
                    const int m = mbase + ma * 16;
                    af[ma][0] = Acu[k2 * SLD + m];
                    af[ma][1] = Acu[k2 * SLD + m + 8];
                    af[ma][2] = Acu[(k2 + 4) * SLD + m];
                    af[ma][3] = Acu[(k2 + 4) * SLD + m + 8];
                }
            }
            // B fragments: 4 x LDS.128 (adjacent natoms packed contiguously)
            uint32_t bf[8][2];
#pragma unroll
            for (int j = 0; j < 4; ++j) {
                uint4 v = *(const uint4*)&Bcu[((s * 8 + nw * 4 + j) * 32 + lane) * 4];
                bf[2 * j][0] = v.x; bf[2 * j][1] = v.y;
                bf[2 * j + 1][0] = v.z; bf[2 * j + 1][1] = v.w;
            }
            // MMA
#pragma unroll
            for (int ma = 0; ma < 2; ++ma)
#pragma unroll
                for (int na = 0; na < 8; ++na)
                    mma16(acc[ma][na], af[ma], bf[na]);

            // consume gather group s -> store into next A buffer, issue group s+1
            if (hn) {
                interp_store(An, s, ga, gb, gc, gd);
                if (s == 0) {
                    ga = *(const uint4*)(inTb + bv.x + c0n + 8);
                    gb = *(const uint4*)(inTb + bv.y + c0n + 8);
                    gc = *(const uint4*)(inTb + bv.z + c0n + 8);
                    gd = *(const uint4*)(inTb + bv.w + c0n + 8);
                }
            }
        }
        cp_wait0();
        __syncthreads();
    }

    // ---- epilogue: stage through smem for coalesced NCHW writes ----
    float* Cs = (float*)smem;   // 64 n x 128 m = 32 KB
    float* ob = out + (size_t)b * COUT * NPIX;
#pragma unroll 1
    for (int nhalf = 0; nhalf < 2; ++nhalf) {
        if (nw == nhalf) {
#pragma unroll
            for (int ma = 0; ma < 2; ++ma)
#pragma unroll
                for (int na = 0; na < 8; ++na)
#pragma unroll
                    for (int d = 0; d < 4; ++d) {
                        int nl = na * 8 + (lane & 3) * 2 + (d & 1);
                        int m = (mw * 2 + ma) * 16 + (lane >> 2) + 8 * (d >> 1);
                        Cs[nl * 128 + m] = acc[ma][na][d];
                    }
        }
        __syncthreads();
#pragma unroll
        for (int it = 0; it < 32; ++it) {
            int idx = tid + it * 256;
            int nl = idx >> 7, m = idx & 127;
            int pp = mtile * MT + m;
            int n = nhalf * 64 + nl;
            if (pp < NPIX)
                ob[(size_t)n * NPIX + pp] = Cs[idx] + bias_s[n];
        }
        __syncthreads();
    }
}

// ---------------------------------------------------------------------------
extern "C" void kernel_launch(void* const* d_in, const int* in_sizes, int n_in,
                              void* d_out, int out_size) {
    const float* inp    = (const float*)d_in[0];
    const float* offset = (const float*)d_in[1];
    const float* mask   = (const float*)d_in[2];
    const float* weight = (const float*)d_in[3];
    const float* bias   = (const float*)d_in[4];
    float* out = (float*)d_out;

    cudaFuncSetAttribute(main_kernel, cudaFuncAttributeMaxDynamicSharedMemorySize,
                         SMEM_TOTAL);

    transpose_kernel<<<BB * HH, 256>>>(inp);
    wpack_kernel<<<(NCHUNK * 2048 + 255) / 256, 256>>>(weight);
    main_kernel<<<dim3(MTILES, BB), 256, SMEM_TOTAL>>>(offset, mask, bias, out);
}

// round 17
// speedup vs baseline: 1.4983x; 1.0348x over previous
#include <cuda_runtime.h>
#include <cuda_fp16.h>
#include <cstdint>

#define BB 8
#define CIN 128
#define COUT 128
#define HH 64
#define WW 64
#define KK 16
#define HO 61
#define WO 61
#define NPIX (HO * WO)        // 3721
#define MT 128
#define MTILES 30
#define NCHUNK 64             // K chunks of 32

#define SLD 136               // As row stride in words (half2 units per k2-row)
#define AS_BUF (16 * SLD)     // words per A buffer (16 k2-rows) = 8704 B

// ---- smem layout (bytes)
#define SM_AS    0                        // 2 x 8704 = 17408
#define SM_BS    17408                    // 2 x 8192 = 16384
#define SM_BIAS  (17408 + 16384)          // 512
#define SMEM_TOTAL (17408 + 16384 + 512)  // 34304

// Scratch (allocation-free: __device__ globals)
__device__ __half g_inT[(size_t)BB * HH * WW * CIN];    // NHWC input, fp16, 8.4 MB
__device__ uint32_t g_wb[(size_t)NCHUNK * 2048];        // frag-packed fp16 weights, 512 KB

static __device__ __forceinline__ void mma16(float* d, const uint32_t* a, const uint32_t* b) {
    asm volatile(
        "mma.sync.aligned.m16n8k16.row.col.f32.f16.f16.f32 "
        "{%0,%1,%2,%3}, {%4,%5,%6,%7}, {%8,%9}, {%0,%1,%2,%3};"
        : "+f"(d[0]), "+f"(d[1]), "+f"(d[2]), "+f"(d[3])
        : "r"(a[0]), "r"(a[1]), "r"(a[2]), "r"(a[3]), "r"(b[0]), "r"(b[1]));
}
static __device__ __forceinline__ void cp16(uint32_t dst, const void* src) {
    asm volatile("cp.async.cg.shared.global [%0], [%1], 16;" :: "r"(dst), "l"(src));
}
static __device__ __forceinline__ void cp_commit() {
    asm volatile("cp.async.commit_group;" ::: "memory");
}
static __device__ __forceinline__ void cp_wait0() {
    asm volatile("cp.async.wait_group 0;" ::: "memory");
}

// ---------------------------------------------------------------------------
// Kernel 1: NCHW fp32 -> NHWC fp16 transpose
// ---------------------------------------------------------------------------
__global__ void transpose_kernel(const float* __restrict__ inp) {
    __shared__ float tile[CIN][WW + 1];
    int by = blockIdx.x;
    int b = by / HH, y = by % HH;
    const float* src = inp + (size_t)b * CIN * HH * WW + (size_t)y * WW;
    for (int i = threadIdx.x; i < CIN * WW; i += blockDim.x) {
        int c = i / WW, x = i % WW;
        tile[c][x] = src[(size_t)c * HH * WW + x];
    }
    __syncthreads();
    __half* dst = g_inT + ((size_t)b * HH + y) * WW * CIN;
    for (int i = threadIdx.x; i < CIN * WW; i += blockDim.x) {
        int x = i / CIN, c = i % CIN;
        dst[(size_t)x * CIN + c] = __float2half(tile[c][x]);
    }
}

// ---------------------------------------------------------------------------
// Kernel 2: weight flip + fp16 + pack in m16n8k16 B-fragment order,
// LDS.128-friendly (same as R12).
// ---------------------------------------------------------------------------
__global__ void wpack_kernel(const float* __restrict__ wgt) {
    int idx = blockIdx.x * blockDim.x + threadIdx.x;
    if (idx >= NCHUNK * 2048) return;
    int w    = idx & 3;
    int lane = (idx >> 2) & 31;
    int na2  = (idx >> 7) & 7;
    int s    = (idx >> 10) & 1;
    int t    = idx >> 11;
    int na_g = na2 * 2 + (w >> 1);
    int r    = w & 1;
    int n = na_g * 8 + (lane >> 2);
    int k0 = s * 16 + (lane & 3) * 2 + r * 8;
    int dk = t >> 2;
    int ki = dk >> 2, kj = dk & 3;
    size_t base = ((size_t)n * CIN + (t & 3) * 32 + k0) * 16 + (3 - ki) * 4 + (3 - kj);
    float v0 = wgt[base];
    float v1 = wgt[base + 16];
    __half2 h2 = __floats2half2_rn(v0, v1);
    g_wb[idx] = *(uint32_t*)&h2;
}

// ---------------------------------------------------------------------------
// Kernel 3: fused bilinear sample (fp16) + fp16 m16n8k16 mma GEMM.
// A tile m-permutation within each 16-row matom:
//   mloc(m) = (m>>4)*16 + (m&7)*2 + ((m>>3)&1)
// so fragment pairs (row r, row r+8) are adjacent -> LDS.64 A-frag loads.
// ---------------------------------------------------------------------------
__global__ void __launch_bounds__(256, 2)
main_kernel(const float* __restrict__ offset, const float* __restrict__ mask,
            const float* __restrict__ bias, float* __restrict__ out) {
    extern __shared__ char smem[];
    uint32_t* As = (uint32_t*)(smem + SM_AS);   // [2][16 k2][SLD] half2 words
    uint32_t* Bs = (uint32_t*)(smem + SM_BS);   // [2][2048]
    float* bias_s = (float*)(smem + SM_BIAS);

    const int tid = threadIdx.x;
    const int mtile = blockIdx.x;
    const int b = blockIdx.y;
    const int lane = tid & 31;
    const int wid = tid >> 5;
    const int mw = wid & 3, nw = wid >> 2;

    if (tid < COUT) bias_s[tid] = bias[tid];

    // fill-thread mapping: 2 threads per pixel, 16 channels each
    const int px = tid >> 1;
    const int h = tid & 1;
    const int p = mtile * MT + px;
    const bool pvalid = p < NPIX;
    const int oh = pvalid ? p / WO : 0;
    const int ow = pvalid ? p % WO : 0;
    const __half* inTb = g_inT + (size_t)b * HH * WW * CIN;

    // permuted m-column for A stores (constant per thread)
    const int mloc = (px & ~15) + ((px & 7) << 1) + ((px >> 3) & 1);

    float acc[2][8][4];
#pragma unroll
    for (int i = 0; i < 2; ++i)
#pragma unroll
        for (int j = 0; j < 8; ++j)
#pragma unroll
            for (int e = 0; e < 4; ++e) acc[i][j][e] = 0.f;

    float4 wv = {0.f, 0.f, 0.f, 0.f};
    int4 bv = {0, 0, 0, 0};
    float pdy = 0.f, pdx = 0.f, pmk = 0.f;

    auto calc_params = [&](int dk, float dy, float dx, float mk) {
        wv = make_float4(0.f, 0.f, 0.f, 0.f);
        bv = make_int4(0, 0, 0, 0);
        if (pvalid) {
            int ki = dk >> 2, kj = dk & 3;
            float y = dy + (float)(ki + oh);
            float x = dx + (float)(kj + ow);
            float y0f = floorf(y), x0f = floorf(x);
            int y0 = (int)y0f, x0 = (int)x0f;
            float wy = y - y0f, wx = x - x0f;
            float w00 = (1.f - wy) * (1.f - wx) * mk;
            float w01 = (1.f - wy) * wx * mk;
            float w10 = wy * (1.f - wx) * mk;
            float w11 = wy * wx * mk;
            bool vy0 = (y0 >= 0) && (y0 < HH);
            bool vy1 = (y0 + 1 >= 0) && (y0 + 1 < HH);
            bool vx0 = (x0 >= 0) && (x0 < WW);
            bool vx1 = (x0 + 1 >= 0) && (x0 + 1 < WW);
            wv.x = (vy0 && vx0) ? w00 : 0.f;
            wv.y = (vy0 && vx1) ? w01 : 0.f;
            wv.z = (vy1 && vx0) ? w10 : 0.f;
            wv.w = (vy1 && vx1) ? w11 : 0.f;
            int y0c = min(max(y0, 0), HH - 1), y1c = min(max(y0 + 1, 0), HH - 1);
            int x0c = min(max(x0, 0), WW - 1), x1c = min(max(x0 + 1, 0), WW - 1);
            bv.x = (y0c * WW + x0c) * CIN;
            bv.y = (y0c * WW + x1c) * CIN;
            bv.z = (y1c * WW + x0c) * CIN;
            bv.w = (y1c * WW + x1c) * CIN;
        }
    };
    auto prefetch_om = [&](int dk) {
        if (pvalid && dk < KK) {
            size_t ob = (((size_t)b * 2 * KK + 2 * dk) * HO + oh) * WO + ow;
            pdy = offset[ob];
            pdx = offset[ob + (size_t)HO * WO];
            pmk = mask[(((size_t)b * KK + dk) * HO + oh) * WO + ow];
        }
    };
    // interp 8 channels (fp32 math), store 4 half2 words (permuted column)
    auto interp_store = [&](uint32_t* An, int s, const uint4& ga, const uint4& gb,
                            const uint4& gc, const uint4& gd) {
        const __half2* ha = (const __half2*)&ga;
        const __half2* hb = (const __half2*)&gb;
        const __half2* hc = (const __half2*)&gc;
        const __half2* hd = (const __half2*)&gd;
#pragma unroll
        for (int w = 0; w < 4; ++w) {
            float2 a = __half22float2(ha[w]);
            float2 b2 = __half22float2(hb[w]);
            float2 c2 = __half22float2(hc[w]);
            float2 d2 = __half22float2(hd[w]);
            float lo = wv.x * a.x + wv.y * b2.x + wv.z * c2.x + wv.w * d2.x;
            float hi = wv.x * a.y + wv.y * b2.y + wv.z * c2.y + wv.w * d2.y;
            __half2 o = __floats2half2_rn(lo, hi);
            An[(h * 8 + s * 4 + w) * SLD + mloc] = *(uint32_t*)&o;
        }
    };

    // ---- prologue: params dk0, prefetch dk1, fill chunk 0 into buffer 0 ----
    {
        float dy0 = 0.f, dx0 = 0.f, mk0 = 0.f;
        if (pvalid) {
            size_t ob = (((size_t)b * 2 * KK) * HO + oh) * WO + ow;
            dy0 = offset[ob];
            dx0 = offset[ob + (size_t)HO * WO];
            mk0 = mask[(((size_t)b * KK) * HO + oh) * WO + ow];
        }
        calc_params(0, dy0, dx0, mk0);
        prefetch_om(1);
        {
            const float4* src = (const float4*)g_wb;
            uint32_t d0 = (uint32_t)__cvta_generic_to_shared(Bs);
#pragma unroll
            for (int j = 0; j < 2; ++j)
                cp16(d0 + (uint32_t)(tid + j * 256) * 16, src + tid + j * 256);
            cp_commit();
        }
#pragma unroll
        for (int s = 0; s < 2; ++s) {
            const int c0 = h * 16 + s * 8;
            uint4 ga = *(const uint4*)(inTb + bv.x + c0);
            uint4 gb = *(const uint4*)(inTb + bv.y + c0);
            uint4 gc = *(const uint4*)(inTb + bv.z + c0);
            uint4 gd = *(const uint4*)(inTb + bv.w + c0);
            interp_store(As, s, ga, gb, gc, gd);
        }
        cp_wait0();
        __syncthreads();
    }

    // ---- main loop ----
    for (int t = 0; t < NCHUNK; ++t) {
        const int cur = t & 1;
        const uint32_t* Acu = As + cur * AS_BUF;
        const uint32_t* Bcu = Bs + cur * 2048;
        uint32_t* An = As + (cur ^ 1) * AS_BUF;
        const bool hn = (t < NCHUNK - 1);

        int c0n = 0;
        uint4 ga, gb, gc, gd;
        if (hn) {
            if (((t + 1) & 3) == 0) {
                int dkn = (t + 1) >> 2;
                calc_params(dkn, pdy, pdx, pmk);
                prefetch_om(dkn + 1);
            }
            const float4* src = (const float4*)(g_wb + (size_t)(t + 1) * 2048);
            uint32_t d0 = (uint32_t)__cvta_generic_to_shared(Bs + (cur ^ 1) * 2048);
#pragma unroll
            for (int j = 0; j < 2; ++j)
                cp16(d0 + (uint32_t)(tid + j * 256) * 16, src + tid + j * 256);
            cp_commit();
            c0n = ((t + 1) & 3) * 32 + h * 16;
            ga = *(const uint4*)(inTb + bv.x + c0n);
            gb = *(const uint4*)(inTb + bv.y + c0n);
            gc = *(const uint4*)(inTb + bv.z + c0n);
            gd = *(const uint4*)(inTb + bv.w + c0n);
        }

#pragma unroll
        for (int s = 0; s < 2; ++s) {
            // A fragments: 4 x LDS.64 (pairs adjacent via m-permutation)
            uint32_t af[2][4];
            {
                const int k2 = s * 8 + (lane & 3);
                const int r2 = (lane >> 2) * 2;
#pragma unroll
                for (int ma = 0; ma < 2; ++ma) {
                    const int mc = (mw * 2 + ma) * 16 + r2;
                    uint2 v0 = *(const uint2*)&Acu[k2 * SLD + mc];
                    uint2 v1 = *(const uint2*)&Acu[(k2 + 4) * SLD + mc];
                    af[ma][0] = v0.x; af[ma][1] = v0.y;
                    af[ma][2] = v1.x; af[ma][3] = v1.y;
                }
            }
            // B fragments: 4 x LDS.128 (adjacent natoms packed contiguously)
            uint32_t bf[8][2];
#pragma unroll
            for (int j = 0; j < 4; ++j) {
                uint4 v = *(const uint4*)&Bcu[((s * 8 + nw * 4 + j) * 32 + lane) * 4];
                bf[2 * j][0] = v.x; bf[2 * j][1] = v.y;
                bf[2 * j + 1][0] = v.z; bf[2 * j + 1][1] = v.w;
            }
            // MMA
#pragma unroll
            for (int ma = 0; ma < 2; ++ma)
#pragma unroll
                for (int na = 0; na < 8; ++na)
                    mma16(acc[ma][na], af[ma], bf[na]);

            // consume gather group s -> store into next A buffer, issue group s+1
            if (hn) {
                interp_store(An, s, ga, gb, gc, gd);
                if (s == 0) {
                    ga = *(const uint4*)(inTb + bv.x + c0n + 8);
                    gb = *(const uint4*)(inTb + bv.y + c0n + 8);
                    gc = *(const uint4*)(inTb + bv.z + c0n + 8);
                    gd = *(const uint4*)(inTb + bv.w + c0n + 8);
                }
            }
        }
        cp_wait0();
        __syncthreads();
    }

    // ---- epilogue: stage through smem for coalesced NCHW writes ----
    float* Cs = (float*)smem;   // 64 n x 128 m = 32 KB
    float* ob = out + (size_t)b * COUT * NPIX;
#pragma unroll 1
    for (int nhalf = 0; nhalf < 2; ++nhalf) {
        if (nw == nhalf) {
#pragma unroll
            for (int ma = 0; ma < 2; ++ma)
#pragma unroll
                for (int na = 0; na < 8; ++na)
#pragma unroll
                    for (int d = 0; d < 4; ++d) {
                        int nl = na * 8 + (lane & 3) * 2 + (d & 1);
                        int m = (mw * 2 + ma) * 16 + (lane >> 2) + 8 * (d >> 1);
                        Cs[nl * 128 + m] = acc[ma][na][d];
                    }
        }
        __syncthreads();
#pragma unroll
        for (int it = 0; it < 32; ++it) {
            int idx = tid + it * 256;
            int nl = idx >> 7, m = idx & 127;
            int pp = mtile * MT + m;
            int n = nhalf * 64 + nl;
            if (pp < NPIX)
                ob[(size_t)n * NPIX + pp] = Cs[idx] + bias_s[n];
        }
        __syncthreads();
    }
}

// ---------------------------------------------------------------------------
extern "C" void kernel_launch(void* const* d_in, const int* in_sizes, int n_in,
                              void* d_out, int out_size) {
    const float* inp    = (const float*)d_in[0];
    const float* offset = (const float*)d_in[1];
    const float* mask   = (const float*)d_in[2];
    const float* weight = (const float*)d_in[3];
    const float* bias   = (const float*)d_in[4];
    float* out = (float*)d_out;

    cudaFuncSetAttribute(main_kernel, cudaFuncAttributeMaxDynamicSharedMemorySize,
                         SMEM_TOTAL);

    transpose_kernel<<<BB * HH, 256>>>(inp);
    wpack_kernel<<<(NCHUNK * 2048 + 255) / 256, 256>>>(weight);
    main_kernel<<<dim3(MTILES, BB), 256, SMEM_TOTAL>>>(offset, mask, bias, out);
}